// round 10
// baseline (speedup 1.0000x reference)
#include <cuda_runtime.h>
#include <math_constants.h>

#define H 1024
#define V 50257
#define L 12
#define TILES ((V + 7) / 8)          // 6283 blocks in k3, 8 rows each

// ---- device scratch (no allocations allowed), 16B-aligned ----
__device__ __align__(16) float g_x[H];         // relu(combine) output
__device__ __align__(16) float g_h[H];         // h_new (aligned copy)
__device__ __align__(16) float g_hh[4 * H];    // W_hh@h0 + b_ih + b_hh
__device__ __align__(16) float g_ps[TILES];    // per-block sum(exp(logit))
__device__ float g_lse;                        // final log-sum-exp

__device__ __forceinline__ float warp_sum(float v) {
#pragma unroll
    for (int o = 16; o; o >>= 1) v += __shfl_xor_sync(0xffffffffu, v, o);
    return v;
}

__device__ __forceinline__ float4 ldcs4(const float4* p) { return __ldcs(p); }

// ============================================================
// Kernel A: 640 blocks x 256 threads, reg-capped.
//   blocks 0..127   : attention (redundant per block) + combine
//   blocks 128..639 : hh gate rows: g_hh[r] = W_hh[r]@h0 + b_ih + b_hh
// launch_bounds caps regs ~40: spills (if any) confined to the
// attention branch; the hh stream keeps 6 blocks/SM.
// ============================================================
__global__ void __launch_bounds__(256, 6)
kA_attn_comb_hh(const int* input,
                const float* __restrict__ h_hidden,
                const float* __restrict__ enc,
                const float* __restrict__ emb,
                const float* __restrict__ attn_W,
                const float* __restrict__ attn_b,
                const float* __restrict__ comb_W,
                const float* __restrict__ comb_b,
                const float* __restrict__ W_hh,
                const float* __restrict__ b_ih,
                const float* __restrict__ b_hh,
                float* __restrict__ attnw_out) {
    const int tid = threadIdx.x;
    const int w = tid >> 5, lane = tid & 31;

    if (blockIdx.x >= 128) {
        __shared__ __align__(16) float4 s_v[256];
        s_v[tid] = ((const float4*)h_hidden)[tid];
        __syncthreads();
        const int r = (blockIdx.x - 128) * 8 + w;      // [0, 4096)
        const float4* row = (const float4*)(W_hh + (size_t)r * H);
        float acc = 0.f;
#pragma unroll
        for (int t = 0; t < 8; t++) {
            float4 a = ldcs4(row + lane + 32 * t);
            float4 b = s_v[lane + 32 * t];
            acc += a.x * b.x + a.y * b.y + a.z * b.z + a.w * b.w;
        }
        acc = warp_sum(acc);
        if (lane == 0) g_hh[r] = acc + b_ih[r] + b_hh[r];
        return;
    }

    // ---- attention + combine (blocks 0..127) ----
    __shared__ __align__(16) float s_in[2 * H];   // [emb ; h0]
    __shared__ __align__(16) float s_cx[2 * H];   // [emb ; applied]
    __shared__ float s_logit[L];
    __shared__ float s_w[L];

    const int idx = input[0];     // low 32 bits of LE int64 index
    const float* e = emb + (size_t)idx * H;
    for (int i = tid; i < H; i += 256) {
        float v = e[i];
        s_in[i] = v;
        s_cx[i] = v;
        s_in[H + i] = h_hidden[i];
    }
    __syncthreads();

    const float4* s_in4 = (const float4*)s_in;
    for (int l = w; l < L; l += 8) {
        const float4* row = (const float4*)(attn_W + (size_t)l * 2 * H);
        float acc = 0.f;
#pragma unroll
        for (int t = 0; t < 16; t++) {
            float4 a = row[lane + 32 * t];
            float4 b = s_in4[lane + 32 * t];
            acc += a.x * b.x + a.y * b.y + a.z * b.z + a.w * b.w;
        }
        acc = warp_sum(acc);
        if (lane == 0) s_logit[l] = acc + attn_b[l];
    }
    __syncthreads();

    if (tid == 0) {
        float m = -1e30f;
#pragma unroll
        for (int l = 0; l < L; l++) m = fmaxf(m, s_logit[l]);
        float s = 0.f;
#pragma unroll
        for (int l = 0; l < L; l++) { float ex = expf(s_logit[l] - m); s_w[l] = ex; s += ex; }
        float inv = 1.f / s;
#pragma unroll
        for (int l = 0; l < L; l++) s_w[l] *= inv;
        if (blockIdx.x == 0)
#pragma unroll
            for (int l = 0; l < L; l++) attnw_out[l] = s_w[l];
    }
    __syncthreads();

    for (int j = tid; j < H; j += 256) {
        float acc = 0.f;
#pragma unroll
        for (int l = 0; l < L; l++) acc += s_w[l] * enc[l * H + j];
        s_cx[H + j] = acc;
    }
    __syncthreads();

    const int r = blockIdx.x * 8 + w;
    const float4* s_cx4 = (const float4*)s_cx;
    const float4* row = (const float4*)(comb_W + (size_t)r * 2 * H);
    float acc = 0.f;
#pragma unroll
    for (int t = 0; t < 16; t++) {
        float4 a = ldcs4(row + lane + 32 * t);
        float4 b = s_cx4[lane + 32 * t];
        acc += a.x * b.x + a.y * b.y + a.z * b.z + a.w * b.w;
    }
    acc = warp_sum(acc);
    if (lane == 0) g_x[r] = fmaxf(acc + comb_b[r], 0.f);
}

// ============================================================
// Kernel B: ih gate rows + LSTM cell, fused. 512 blocks x 256.
// Block b owns hidden units u0=2b, u1=2b+1. Warp w computes gate
// row (w&3) of unit (w>>2): dot(W_ih[gate*H + j], x). Gates land
// in smem; threads 0..1 then do the cell math for the 2 units.
// ============================================================
__global__ void __launch_bounds__(256, 6)
kB_ih_cell(const float* __restrict__ W_ih,
           const float* __restrict__ c_hidden,
           float* __restrict__ h_new,
           float* __restrict__ c_new) {
    __shared__ __align__(16) float4 s_v[256];     // x vector
    __shared__ float s_gate[8];                   // [unit][gate]
    const int tid = threadIdx.x;
    const int w = tid >> 5, lane = tid & 31;
    s_v[tid] = ((const float4*)g_x)[tid];
    __syncthreads();

    const int u = w >> 2;                 // 0..1 local unit
    const int g = w & 3;                  // gate index
    const int j = blockIdx.x * 2 + u;     // hidden unit
    const int r = g * H + j;              // W_ih row
    const float4* row = (const float4*)(W_ih + (size_t)r * H);
    float acc = 0.f;
#pragma unroll
    for (int t = 0; t < 8; t++) {
        float4 a = ldcs4(row + lane + 32 * t);
        float4 b = s_v[lane + 32 * t];
        acc += a.x * b.x + a.y * b.y + a.z * b.z + a.w * b.w;
    }
    acc = warp_sum(acc);
    if (lane == 0) s_gate[u * 4 + g] = acc;
    __syncthreads();

    if (tid < 2) {
        const int jj = blockIdx.x * 2 + tid;
        float gi = s_gate[tid * 4 + 0] + g_hh[jj];
        float gf = s_gate[tid * 4 + 1] + g_hh[H + jj];
        float gg = s_gate[tid * 4 + 2] + g_hh[2 * H + jj];
        float go = s_gate[tid * 4 + 3] + g_hh[3 * H + jj];
        float si = 1.f / (1.f + expf(-gi));
        float sf = 1.f / (1.f + expf(-gf));
        float so = 1.f / (1.f + expf(-go));
        float c = sf * c_hidden[jj] + si * tanhf(gg);
        float h = so * tanhf(c);
        c_new[jj] = c;
        h_new[jj] = h;
        g_h[jj] = h;
    }
}

// ============================================================
// Kernel 3: output projection (50257 x 1024), 8 rows/block,
// one warp per row; per-block sum(exp(logit)) partial.
// Clean epilogue — no fences/atomics. Bounded logits: plain exp.
// ============================================================
__global__ void k3_out(const float* __restrict__ out_W,
                       const float* __restrict__ out_b,
                       float* __restrict__ logits) {
    __shared__ __align__(16) float4 s_h[256];
    __shared__ float s_l[8];
    const int tid = threadIdx.x;
    s_h[tid] = ((const float4*)g_h)[tid];
    __syncthreads();

    const int w = tid >> 5, lane = tid & 31;
    const int r = blockIdx.x * 8 + w;
    float l = -CUDART_INF_F;
    if (r < V) {
        const float4* row = (const float4*)(out_W + (size_t)r * H);
        float acc = 0.f;
#pragma unroll
        for (int t = 0; t < 8; t++) {
            float4 a = ldcs4(row + lane + 32 * t);
            float4 b = s_h[lane + 32 * t];
            acc += a.x * b.x + a.y * b.y + a.z * b.z + a.w * b.w;
        }
        acc = warp_sum(acc);
        if (lane == 0) {
            l = acc + out_b[r];
            logits[r] = l;
        }
    }
    if (lane == 0) s_l[w] = l;
    __syncthreads();
    if (tid == 0) {
        float s = 0.f;
#pragma unroll
        for (int i = 0; i < 8; i++) {
            float v = s_l[i];
            if (v != -CUDART_INF_F) s += expf(v);
        }
        g_ps[blockIdx.x] = s;
    }
}

// ============================================================
// Kernel 3.5: reduce 6283 L2-resident partials -> g_lse.
// ============================================================
__global__ void k_lse() {
    __shared__ float s_part[8];
    const int tid = threadIdx.x;
    const int w = tid >> 5, lane = tid & 31;
    float s = 0.f;
    for (int i = tid; i < TILES; i += 256) s += g_ps[i];
    s = warp_sum(s);
    if (lane == 0) s_part[w] = s;
    __syncthreads();
    if (tid == 0) {
        float tot = 0.f;
#pragma unroll
        for (int i = 0; i < 8; i++) tot += s_part[i];
        g_lse = logf(tot);
    }
}

// ============================================================
// Kernel 4: logp[i] = logits[i] - g_lse (L2-resident elementwise)
// ============================================================
__global__ void k4_sub(float* __restrict__ logp) {
    const int i = blockIdx.x * 256 + threadIdx.x;
    if (i < V) logp[i] -= g_lse;
}

// ============================================================
extern "C" void kernel_launch(void* const* d_in, const int* in_sizes, int n_in,
                              void* d_out, int out_size) {
    const int*   input   = (const int*)  d_in[0];
    const float* h_hid   = (const float*)d_in[1];
    const float* c_hid   = (const float*)d_in[2];
    const float* enc     = (const float*)d_in[3];
    const float* emb     = (const float*)d_in[4];
    const float* attn_W  = (const float*)d_in[5];
    const float* attn_b  = (const float*)d_in[6];
    const float* comb_W  = (const float*)d_in[7];
    const float* comb_b  = (const float*)d_in[8];
    const float* W_ih    = (const float*)d_in[9];
    const float* W_hh    = (const float*)d_in[10];
    const float* b_ih    = (const float*)d_in[11];
    const float* b_hh    = (const float*)d_in[12];
    const float* out_W   = (const float*)d_in[13];
    const float* out_b   = (const float*)d_in[14];

    float* out   = (float*)d_out;
    float* logp  = out;                 // [V]
    float* h_new = out + V;             // [H]
    float* c_new = out + V + H;         // [H]
    float* attnw = out + V + 2 * H;     // [L]

    kA_attn_comb_hh<<<640, 256>>>(input, h_hid, enc, emb, attn_W, attn_b,
                                  comb_W, comb_b, W_hh, b_ih, b_hh, attnw);
    kB_ih_cell<<<512, 256>>>(W_ih, c_hid, h_new, c_new);
    k3_out<<<TILES, 256>>>(out_W, out_b, logp);
    k_lse<<<1, 256>>>();
    k4_sub<<<(V + 255) / 256, 256>>>(logp);
}

// round 11
// speedup vs baseline: 1.0786x; 1.0786x over previous
#include <cuda_runtime.h>
#include <math_constants.h>

#define H 1024
#define V 50257
#define L 12
#define TILES ((V + 7) / 8)          // 6283 blocks in k3, 8 rows each

// ---- device scratch (no allocations allowed), 16B-aligned ----
__device__ __align__(16) float g_x[H];         // relu(combine) output
__device__ __align__(16) float g_h[H];         // h_new (aligned copy)
__device__ __align__(16) float g_hh[4 * H];    // W_hh@h0 + b_ih + b_hh
__device__ float g_sum;                        // global sum(exp(logit)) accumulator

__device__ __forceinline__ float warp_sum(float v) {
#pragma unroll
    for (int o = 16; o; o >>= 1) v += __shfl_xor_sync(0xffffffffu, v, o);
    return v;
}

__device__ __forceinline__ float4 ldcs4(const float4* p) { return __ldcs(p); }

// ============================================================
// Kernel 1:
//   blocks 0..127   : attention + combine (8 rows each)
//   blocks 128..639 : hh gate half: g_hh[r] = W_hh[r]@h0 + b_ih[r] + b_hh[r]
// Block 0 also resets g_sum for this graph replay (runs before k3).
// ============================================================
__global__ void k1_attn_comb_hh(const int* input,
                                const float* __restrict__ h_hidden,
                                const float* __restrict__ enc,
                                const float* __restrict__ emb,
                                const float* __restrict__ attn_W,
                                const float* __restrict__ attn_b,
                                const float* __restrict__ comb_W,
                                const float* __restrict__ comb_b,
                                const float* __restrict__ W_hh,
                                const float* __restrict__ b_ih,
                                const float* __restrict__ b_hh,
                                float* __restrict__ attnw_out) {
    const int tid = threadIdx.x;
    const int w = tid >> 5, lane = tid & 31;

    if (blockIdx.x >= 128) {
        __shared__ __align__(16) float4 s_h[256];
        s_h[tid] = ((const float4*)h_hidden)[tid];
        __syncthreads();
        const int r = (blockIdx.x - 128) * 8 + w;      // [0, 4096)
        const float4* row = (const float4*)(W_hh + (size_t)r * H);
        float acc = 0.f;
#pragma unroll
        for (int t = 0; t < 8; t++) {
            float4 a = ldcs4(row + lane + 32 * t);
            float4 b = s_h[lane + 32 * t];
            acc += a.x * b.x + a.y * b.y + a.z * b.z + a.w * b.w;
        }
        acc = warp_sum(acc);
        if (lane == 0) g_hh[r] = acc + b_ih[r] + b_hh[r];
        return;
    }

    __shared__ __align__(16) float s_in[2 * H];   // [emb ; h0]
    __shared__ __align__(16) float s_cx[2 * H];   // [emb ; applied]
    __shared__ float s_logit[L];
    __shared__ float s_w[L];

    if (blockIdx.x == 0 && tid == 0) g_sum = 0.f;  // reset accumulator per replay

    const int idx = input[0];     // low 32 bits of LE int64 index
    const float* e = emb + (size_t)idx * H;
    for (int i = tid; i < H; i += 256) {
        float v = e[i];
        s_in[i] = v;
        s_cx[i] = v;
        s_in[H + i] = h_hidden[i];
    }
    __syncthreads();

    const float4* s_in4 = (const float4*)s_in;
    for (int l = w; l < L; l += 8) {
        const float4* row = (const float4*)(attn_W + (size_t)l * 2 * H);
        float acc = 0.f;
#pragma unroll
        for (int t = 0; t < 16; t++) {
            float4 a = row[lane + 32 * t];
            float4 b = s_in4[lane + 32 * t];
            acc += a.x * b.x + a.y * b.y + a.z * b.z + a.w * b.w;
        }
        acc = warp_sum(acc);
        if (lane == 0) s_logit[l] = acc + attn_b[l];
    }
    __syncthreads();

    if (tid == 0) {
        float m = -1e30f;
#pragma unroll
        for (int l = 0; l < L; l++) m = fmaxf(m, s_logit[l]);
        float s = 0.f;
#pragma unroll
        for (int l = 0; l < L; l++) { float ex = expf(s_logit[l] - m); s_w[l] = ex; s += ex; }
        float inv = 1.f / s;
#pragma unroll
        for (int l = 0; l < L; l++) s_w[l] *= inv;
        if (blockIdx.x == 0)
#pragma unroll
            for (int l = 0; l < L; l++) attnw_out[l] = s_w[l];
    }
    __syncthreads();

    for (int j = tid; j < H; j += 256) {
        float acc = 0.f;
#pragma unroll
        for (int l = 0; l < L; l++) acc += s_w[l] * enc[l * H + j];
        s_cx[H + j] = acc;
    }
    __syncthreads();

    const int r = blockIdx.x * 8 + w;
    const float4* s_cx4 = (const float4*)s_cx;
    const float4* row = (const float4*)(comb_W + (size_t)r * 2 * H);
    float acc = 0.f;
#pragma unroll
    for (int t = 0; t < 16; t++) {
        float4 a = ldcs4(row + lane + 32 * t);
        float4 b = s_cx4[lane + 32 * t];
        acc += a.x * b.x + a.y * b.y + a.z * b.z + a.w * b.w;
    }
    acc = warp_sum(acc);
    if (lane == 0) g_x[r] = fmaxf(acc + comb_b[r], 0.f);
}

// ============================================================
// Kernel 2: ih-half of gates + LSTM cell, fused.
// One warp per hidden unit j (4 W_ih rows, processed pairwise).
// ============================================================
__global__ void k2_gates_cell(const float* __restrict__ c_hidden,
                              const float* __restrict__ W_ih,
                              float* __restrict__ h_new,
                              float* __restrict__ c_new) {
    __shared__ __align__(16) float4 s_x[256];
    const int tid = threadIdx.x;
    s_x[tid] = ((const float4*)g_x)[tid];
    __syncthreads();

    const int w = tid >> 5, lane = tid & 31;
    const int j = blockIdx.x * 8 + w;

    float gate[4];
#pragma unroll
    for (int gp = 0; gp < 2; gp++) {
        const float4* r0 = (const float4*)(W_ih + (size_t)((2 * gp) * H + j) * H);
        const float4* r1 = (const float4*)(W_ih + (size_t)((2 * gp + 1) * H + j) * H);
        float a0 = 0.f, a1 = 0.f;
#pragma unroll
        for (int t = 0; t < 8; t++) {
            float4 w0 = ldcs4(r0 + lane + 32 * t);
            float4 w1 = ldcs4(r1 + lane + 32 * t);
            float4 xb = s_x[lane + 32 * t];
            a0 += w0.x * xb.x + w0.y * xb.y + w0.z * xb.z + w0.w * xb.w;
            a1 += w1.x * xb.x + w1.y * xb.y + w1.z * xb.z + w1.w * xb.w;
        }
        gate[2 * gp]     = warp_sum(a0);
        gate[2 * gp + 1] = warp_sum(a1);
    }
    if (lane == 0) {
        float gi = gate[0] + g_hh[j];
        float gf = gate[1] + g_hh[H + j];
        float gg = gate[2] + g_hh[2 * H + j];
        float go = gate[3] + g_hh[3 * H + j];
        float si = 1.f / (1.f + expf(-gi));
        float sf = 1.f / (1.f + expf(-gf));
        float so = 1.f / (1.f + expf(-go));
        float c = sf * c_hidden[j] + si * tanhf(gg);
        float h = so * tanhf(c);
        c_new[j] = c;
        h_new[j] = h;
        g_h[j] = h;
    }
}

// ============================================================
// Kernel 3: output projection (50257 x 1024), 8 rows/block,
// one warp per row. Per-block sum(exp) partial goes out via a
// single fire-and-forget atomicAdd (REDG) — no fence, no drain.
// Logits are bounded (|l| <~ 32) so plain exp is safe.
// ============================================================
__global__ void k3_out(const float* __restrict__ out_W,
                       const float* __restrict__ out_b,
                       float* __restrict__ logits) {
    __shared__ __align__(16) float4 s_h[256];
    __shared__ float s_l[8];
    const int tid = threadIdx.x;
    s_h[tid] = ((const float4*)g_h)[tid];
    __syncthreads();

    const int w = tid >> 5, lane = tid & 31;
    const int r = blockIdx.x * 8 + w;
    float l = -CUDART_INF_F;
    if (r < V) {
        const float4* row = (const float4*)(out_W + (size_t)r * H);
        float acc = 0.f;
#pragma unroll
        for (int t = 0; t < 8; t++) {
            float4 a = ldcs4(row + lane + 32 * t);
            float4 b = s_h[lane + 32 * t];
            acc += a.x * b.x + a.y * b.y + a.z * b.z + a.w * b.w;
        }
        acc = warp_sum(acc);
        if (lane == 0) {
            l = acc + out_b[r];
            logits[r] = l;
        }
    }
    if (lane == 0) s_l[w] = l;
    __syncthreads();
    if (tid == 0) {
        float s = 0.f;
#pragma unroll
        for (int i = 0; i < 8; i++) {
            float v = s_l[i];
            if (v != -CUDART_INF_F) s += expf(v);
        }
        atomicAdd(&g_sum, s);          // REDG: no return value, no fence
    }
}

// ============================================================
// Kernel 4: logp[i] = logits[i] - log(g_sum). 197 blocks x 256.
// ============================================================
__global__ void k4_sub(float* __restrict__ logp) {
    __shared__ float s_lse;
    const int tid = threadIdx.x;
    if (tid == 0) s_lse = logf(g_sum);
    __syncthreads();
    const float lse = s_lse;
    const int i = blockIdx.x * 256 + tid;
    if (i < V) logp[i] -= lse;
}

// ============================================================
extern "C" void kernel_launch(void* const* d_in, const int* in_sizes, int n_in,
                              void* d_out, int out_size) {
    const int*   input   = (const int*)  d_in[0];
    const float* h_hid   = (const float*)d_in[1];
    const float* c_hid   = (const float*)d_in[2];
    const float* enc     = (const float*)d_in[3];
    const float* emb     = (const float*)d_in[4];
    const float* attn_W  = (const float*)d_in[5];
    const float* attn_b  = (const float*)d_in[6];
    const float* comb_W  = (const float*)d_in[7];
    const float* comb_b  = (const float*)d_in[8];
    const float* W_ih    = (const float*)d_in[9];
    const float* W_hh    = (const float*)d_in[10];
    const float* b_ih    = (const float*)d_in[11];
    const float* b_hh    = (const float*)d_in[12];
    const float* out_W   = (const float*)d_in[13];
    const float* out_b   = (const float*)d_in[14];

    float* out   = (float*)d_out;
    float* logp  = out;                 // [V]
    float* h_new = out + V;             // [H]
    float* c_new = out + V + H;         // [H]
    float* attnw = out + V + 2 * H;     // [L]

    k1_attn_comb_hh<<<128 + 512, 256>>>(input, h_hid, enc, emb, attn_W, attn_b,
                                        comb_W, comb_b, W_hh, b_ih, b_hh, attnw);
    k2_gates_cell<<<128, 256>>>(c_hid, W_ih, h_new, c_new);
    k3_out<<<TILES, 256>>>(out_W, out_b, logp);
    k4_sub<<<(V + 255) / 256, 256>>>(logp);
}